// round 1
// baseline (speedup 1.0000x reference)
#include <cuda_runtime.h>

// Problem constants
#define Bsz  2
#define Cc   64
#define Hh   128
#define Ww   256
#define HG   122880          // grid rows = L*KH
#define LOUT 40960           // output rows after stride-3 depthwise
#define TL   8               // output rows per block
#define NR   (3*TL + 2)      // local sampled rows incl. +/-1 halo  (26)
#define NP   (NR * 3)        // local sampled points (rows x 3 cols) (78)

// Scratch: x transposed to [B, H, W, C] so a bilinear tap is 64 contiguous floats.
__device__ float g_xT[Bsz * Hh * Ww * Cc];

// ---------------------------------------------------------------------------
// Kernel 1: NCHW -> NHWC transpose of x (16.8 MB, trivial cost, enables
// fully-coalesced 256B taps in the gather).
// grid: (W/32, C/32, B*H), block (32,8)
// ---------------------------------------------------------------------------
__global__ void transpose_k(const float* __restrict__ x) {
    __shared__ float tile[32][33];
    int w0 = blockIdx.x * 32;
    int c0 = blockIdx.y * 32;
    int bh = blockIdx.z;
    int b  = bh >> 7;          // H = 128
    int h  = bh & 127;
    int tx = threadIdx.x, ty = threadIdx.y;
#pragma unroll
    for (int i = 0; i < 4; i++) {
        int c = c0 + ty + i * 8;
        tile[ty + i * 8][tx] = x[((b * Cc + c) * Hh + h) * Ww + w0 + tx];
    }
    __syncthreads();
#pragma unroll
    for (int i = 0; i < 4; i++) {
        int w = w0 + ty + i * 8;
        g_xT[((b * Hh + h) * Ww + w) * Cc + c0 + tx] = tile[tx][ty + i * 8];
    }
}

// ---------------------------------------------------------------------------
// Kernel 2: fully fused grid_sample + spatial attention + depthwise(stride 3)
// + pointwise. One block = TL=8 output rows for one batch.
// grid: (LOUT/TL, B), block 256.
// ---------------------------------------------------------------------------
__global__ __launch_bounds__(256) void fused_k(
    const float* __restrict__ grid,
    const float* __restrict__ sa_w, const float* __restrict__ sa_b,
    const float* __restrict__ dw_w, const float* __restrict__ dw_b,
    const float* __restrict__ pw_w, const float* __restrict__ pw_b,
    float* __restrict__ out)
{
    __shared__ __align__(16) float v_sm[NP * 64];     // sampled vectors
    __shared__ float savg[NP];
    __shared__ float smax_[NP];
    __shared__ float m_att[TL * 3 * 3];               // (1 + sigmoid) gates
    __shared__ __align__(16) float z_sm[TL * 64];     // depthwise results
    __shared__ __align__(16) float pw_sm[64 * 68];    // pw_w, row-padded to 68
    __shared__ float dw_sm[64 * 9];
    __shared__ float o_sm[64 * 9];                    // [o][l], padded

    const int t  = threadIdx.x;
    const int b  = blockIdx.y;
    const int l0 = blockIdx.x * TL;
    const float* __restrict__ xb = g_xT + (size_t)b * (Hh * Ww * Cc);

    // Stage weights into smem (conflict-free padded layouts)
    for (int i = t; i < 64 * 64; i += 256)
        pw_sm[(i >> 6) * 68 + (i & 63)] = pw_w[i];
    for (int i = t; i < 576; i += 256)
        dw_sm[i] = dw_w[i];

    // ---- Stage 1: bilinear gather for NP points (incl. halo), + avg/max ----
    // 16 threads per point; each lane owns 4 channels (one float4 per tap).
    const int grp  = t >> 4;      // 0..15 : point group
    const int lane = t & 15;
    const int co   = lane * 4;    // channel offset

    for (int p = grp; p < NP; p += 16) {
        int r  = p / 3;
        int kw = p - r * 3;
        int h  = 3 * l0 - 1 + r;          // global grid row (can be -1 / HG)
        float4 a4 = make_float4(0.f, 0.f, 0.f, 0.f);
        if (h >= 0 && h < HG) {
            float gxr = __ldg(&grid[(h * 3 + kw) * 2 + 0]);
            float gyr = __ldg(&grid[(h * 3 + kw) * 2 + 1]);
            float gx = (gxr + 1.0f) * 128.0f - 0.5f;   // W/2 = 128
            float gy = (gyr + 1.0f) * 64.0f  - 0.5f;   // H/2 = 64
            float x0f = floorf(gx), y0f = floorf(gy);
            float wx = gx - x0f, wy = gy - y0f;
            int x0 = (int)x0f, y0 = (int)y0f;
            float w00 = (1.f - wx) * (1.f - wy);
            float w10 = wx * (1.f - wy);
            float w01 = (1.f - wx) * wy;
            float w11 = wx * wy;
            bool vx0 = (unsigned)x0       < (unsigned)Ww;
            bool vx1 = (unsigned)(x0 + 1) < (unsigned)Ww;
            if ((unsigned)y0 < (unsigned)Hh) {
                const float* row = xb + (size_t)y0 * (Ww * 64);
                if (vx0) {
                    float4 v = *(const float4*)(row + x0 * 64 + co);
                    a4.x = fmaf(w00, v.x, a4.x); a4.y = fmaf(w00, v.y, a4.y);
                    a4.z = fmaf(w00, v.z, a4.z); a4.w = fmaf(w00, v.w, a4.w);
                }
                if (vx1) {
                    float4 v = *(const float4*)(row + (x0 + 1) * 64 + co);
                    a4.x = fmaf(w10, v.x, a4.x); a4.y = fmaf(w10, v.y, a4.y);
                    a4.z = fmaf(w10, v.z, a4.z); a4.w = fmaf(w10, v.w, a4.w);
                }
            }
            if ((unsigned)(y0 + 1) < (unsigned)Hh) {
                const float* row = xb + (size_t)(y0 + 1) * (Ww * 64);
                if (vx0) {
                    float4 v = *(const float4*)(row + x0 * 64 + co);
                    a4.x = fmaf(w01, v.x, a4.x); a4.y = fmaf(w01, v.y, a4.y);
                    a4.z = fmaf(w01, v.z, a4.z); a4.w = fmaf(w01, v.w, a4.w);
                }
                if (vx1) {
                    float4 v = *(const float4*)(row + (x0 + 1) * 64 + co);
                    a4.x = fmaf(w11, v.x, a4.x); a4.y = fmaf(w11, v.y, a4.y);
                    a4.z = fmaf(w11, v.z, a4.z); a4.w = fmaf(w11, v.w, a4.w);
                }
            }
        }
        // channel avg / max (true max of sampled values, incl. negatives;
        // out-of-range halo rows give exact zeros = conv zero-padding)
        float sum = a4.x + a4.y + a4.z + a4.w;
        float mx  = fmaxf(fmaxf(a4.x, a4.y), fmaxf(a4.z, a4.w));
#pragma unroll
        for (int off = 8; off; off >>= 1) {
            sum += __shfl_xor_sync(0xFFFFFFFFu, sum, off);
            mx = fmaxf(mx, __shfl_xor_sync(0xFFFFFFFFu, mx, off));
        }
        *(float4*)&v_sm[p * 64 + co] = a4;
        if (lane == 0) { savg[p] = sum * (1.0f / 64.0f); smax_[p] = mx; }
    }
    __syncthreads();

    // ---- Stage 2: spatial attention gates for the 3*TL x 3 interior ----
    if (t < TL * 3 * 3) {
        int ra = t / 3, kw = t - ra * 3;   // interior row ra -> v-row ra+1
        float acc = __ldg(sa_b);
#pragma unroll
        for (int kh = 0; kh < 3; kh++) {
            int rr = ra + kh;              // v-row of s input (0..NR-1)
#pragma unroll
            for (int k2 = 0; k2 < 3; k2++) {
                int cc = kw + k2 - 1;      // column with zero padding
                if (cc >= 0 && cc < 3) {
                    int p = rr * 3 + cc;
                    acc += __ldg(&sa_w[kh * 3 + k2])     * savg[p]
                         + __ldg(&sa_w[9 + kh * 3 + k2]) * smax_[p];
                }
            }
        }
        m_att[t] = 1.0f + 1.0f / (1.0f + expf(-acc));   // y = (1+a)*v
    }
    __syncthreads();

    // ---- Stage 3: depthwise 3x3 (stride handled by patch layout) ----
    {
        int c = t & 63, lg = t >> 6;
        float dwc[9];
#pragma unroll
        for (int k = 0; k < 9; k++) dwc[k] = dw_sm[c * 9 + k];
        float db = __ldg(&dw_b[c]);
        for (int l = lg; l < TL; l += 4) {
            float acc = db;
#pragma unroll
            for (int kh = 0; kh < 3; kh++)
#pragma unroll
                for (int kw = 0; kw < 3; kw++) {
                    int ra = 3 * l + kh;
                    acc = fmaf(dwc[kh * 3 + kw] * m_att[ra * 3 + kw],
                               v_sm[((ra + 1) * 3 + kw) * 64 + c], acc);
                }
            z_sm[l * 64 + c] = acc;
        }
    }
    __syncthreads();

    // ---- Stage 4: pointwise 64x64 (each thread: 1 o, 2 l, shared pw load) --
    {
        int o = t & 63, lg = t >> 6;
        float pb = __ldg(&pw_b[o]);
        float acc0 = pb, acc1 = pb;
        const int lA = lg, lB = lg + 4;
#pragma unroll
        for (int cc = 0; cc < 64; cc += 4) {
            float4 wv = *(const float4*)&pw_sm[o * 68 + cc];
            float4 z0 = *(const float4*)&z_sm[lA * 64 + cc];
            float4 z1 = *(const float4*)&z_sm[lB * 64 + cc];
            acc0 = fmaf(wv.x, z0.x, acc0); acc0 = fmaf(wv.y, z0.y, acc0);
            acc0 = fmaf(wv.z, z0.z, acc0); acc0 = fmaf(wv.w, z0.w, acc0);
            acc1 = fmaf(wv.x, z1.x, acc1); acc1 = fmaf(wv.y, z1.y, acc1);
            acc1 = fmaf(wv.z, z1.z, acc1); acc1 = fmaf(wv.w, z1.w, acc1);
        }
        o_sm[o * 9 + lA] = acc0;
        o_sm[o * 9 + lB] = acc1;
    }
    __syncthreads();

    // ---- Stage 5: coalesced write-out out[b, o, l0..l0+7] ----
    for (int i = t; i < 64 * TL; i += 256) {
        int o = i >> 3, j = i & 7;
        out[((size_t)b * 64 + o) * LOUT + l0 + j] = o_sm[o * 9 + j];
    }
}

// ---------------------------------------------------------------------------
extern "C" void kernel_launch(void* const* d_in, const int* in_sizes, int n_in,
                              void* d_out, int out_size) {
    (void)in_sizes; (void)n_in; (void)out_size;
    const float* x    = (const float*)d_in[0];
    const float* grid = (const float*)d_in[1];
    const float* sa_w = (const float*)d_in[2];
    const float* sa_b = (const float*)d_in[3];
    const float* dw_w = (const float*)d_in[4];
    const float* dw_b = (const float*)d_in[5];
    const float* pw_w = (const float*)d_in[6];
    const float* pw_b = (const float*)d_in[7];
    float* out = (float*)d_out;

    dim3 tb(32, 8);
    dim3 tg(Ww / 32, Cc / 32, Bsz * Hh);
    transpose_k<<<tg, tb>>>(x);

    dim3 mg(LOUT / TL, Bsz);
    fused_k<<<mg, 256>>>(grid, sa_w, sa_b, dw_w, dw_b, pw_w, pw_b, out);
}

// round 3
// speedup vs baseline: 1.0319x; 1.0319x over previous
#include <cuda_runtime.h>
#include <cuda_fp16.h>

// Problem constants
#define Bsz  2
#define Cc   64
#define Hh   128
#define Ww   256
#define HG   122880          // grid rows = L*KH
#define LOUT 40960           // output rows after stride-3 depthwise
#define TL   16              // output rows per block
#define NR   (3*TL + 2)      // local sampled rows incl. +/-1 halo  (50)
#define NP   (NR * 3)        // local sampled points (rows x 3 cols) (150)
#define NP_PAD 160           // NP rounded up to a multiple of 32 (uniform warp trips)

// Scratch: x transposed to [B, H, W, C] in fp16 so a bilinear tap is one
// 128B wavefront (64 contiguous halves).
__device__ __half g_xT[Bsz * Hh * Ww * Cc];

// ---------------------------------------------------------------------------
// Kernel 1: NCHW fp32 -> NHWC fp16 transpose of x.
// grid: (W/32, C/32, B*H), block (32,8)
// ---------------------------------------------------------------------------
__global__ void transpose_k(const float* __restrict__ x) {
    __shared__ float tile[32][33];
    int w0 = blockIdx.x * 32;
    int c0 = blockIdx.y * 32;
    int bh = blockIdx.z;
    int b  = bh >> 7;          // H = 128
    int h  = bh & 127;
    int tx = threadIdx.x, ty = threadIdx.y;
#pragma unroll
    for (int i = 0; i < 4; i++) {
        int c = c0 + ty + i * 8;
        tile[ty + i * 8][tx] = x[((b * Cc + c) * Hh + h) * Ww + w0 + tx];
    }
    __syncthreads();
#pragma unroll
    for (int i = 0; i < 4; i++) {
        int w = w0 + ty + i * 8;
        g_xT[((size_t)(b * Hh + h) * Ww + w) * Cc + c0 + tx] =
            __float2half_rn(tile[tx][ty + i * 8]);
    }
}

// ---------------------------------------------------------------------------
// Kernel 2: fully fused grid_sample + spatial attention + depthwise(stride 3)
// + pointwise. One block = TL=16 output rows for one batch.
// grid: (LOUT/TL, B), block 256.
// ---------------------------------------------------------------------------
__global__ __launch_bounds__(256) void fused_k(
    const float* __restrict__ grid,
    const float* __restrict__ sa_w, const float* __restrict__ sa_b,
    const float* __restrict__ dw_w, const float* __restrict__ dw_b,
    const float* __restrict__ pw_w, const float* __restrict__ pw_b,
    float* __restrict__ out)
{
    __shared__ __align__(16) __half2 v_sm2[NP * 32];  // sampled vectors (fp16)
    __shared__ float savg[NP];
    __shared__ float smax_[NP];
    __shared__ float m_att[TL * 3 * 3];               // (1 + sigmoid) gates
    __shared__ __align__(16) float z_sm[TL * 64];     // depthwise results
    __shared__ __align__(16) float pw_sm[64 * 68];    // pw_w, row-padded to 68
    __shared__ float dw_sm[64 * 9];
    __shared__ float o_sm[64 * (TL + 1)];             // [o][l], padded

    const int t  = threadIdx.x;
    const int b  = blockIdx.y;
    const int l0 = blockIdx.x * TL;
    const __half* __restrict__ xb = g_xT + (size_t)b * (Hh * Ww * Cc);

    // Stage weights into smem (conflict-free padded layouts)
    for (int i = t; i < 64 * 64; i += 256)
        pw_sm[(i >> 6) * 68 + (i & 63)] = pw_w[i];
    for (int i = t; i < 576; i += 256)
        dw_sm[i] = dw_w[i];

    // ---- Stage 1: bilinear gather for NP points (incl. halo), + avg/max ----
    // 8 lanes per point; each lane owns 8 channels (one 16B uint4 per tap).
    // Loop bound padded to NP_PAD so every lane of a warp runs the same trip
    // count (the in-loop __shfl_xor_sync requires full-warp participation).
    const int grp  = t >> 3;      // 0..31 : point group
    const int lane = t & 7;
    const int co   = lane * 8;    // channel offset (halves)

    for (int p = grp; p < NP_PAD; p += 32) {
        const bool active = (p < NP);
        float acc[8];
#pragma unroll
        for (int k = 0; k < 8; k++) acc[k] = 0.f;
        if (active) {
            int r  = p / 3;
            int kw = p - r * 3;
            int h  = 3 * l0 - 1 + r;      // global grid row (can be -1 / >=HG)
            if (h >= 0 && h < HG) {
                float gxr = __ldg(&grid[(h * 3 + kw) * 2 + 0]);
                float gyr = __ldg(&grid[(h * 3 + kw) * 2 + 1]);
                float gx = (gxr + 1.0f) * 128.0f - 0.5f;   // W/2 = 128
                float gy = (gyr + 1.0f) * 64.0f  - 0.5f;   // H/2 = 64
                float x0f = floorf(gx), y0f = floorf(gy);
                float wx = gx - x0f, wy = gy - y0f;
                int x0 = (int)x0f, y0 = (int)y0f;
                float w00 = (1.f - wx) * (1.f - wy);
                float w10 = wx * (1.f - wy);
                float w01 = (1.f - wx) * wy;
                float w11 = wx * wy;
                bool vx0 = (unsigned)x0       < (unsigned)Ww;
                bool vx1 = (unsigned)(x0 + 1) < (unsigned)Ww;
#pragma unroll
                for (int dy = 0; dy < 2; dy++) {
                    int yy = y0 + dy;
                    if ((unsigned)yy < (unsigned)Hh) {
                        const __half* row = xb + (size_t)yy * (Ww * 64);
                        float wA = dy ? w01 : w00;
                        float wB = dy ? w11 : w10;
                        if (vx0) {
                            const __half2* hp = (const __half2*)(row + x0 * 64 + co);
#pragma unroll
                            for (int k = 0; k < 4; k++) {
                                float2 f = __half22float2(hp[k]);
                                acc[2*k]   = fmaf(wA, f.x, acc[2*k]);
                                acc[2*k+1] = fmaf(wA, f.y, acc[2*k+1]);
                            }
                        }
                        if (vx1) {
                            const __half2* hp = (const __half2*)(row + (x0 + 1) * 64 + co);
#pragma unroll
                            for (int k = 0; k < 4; k++) {
                                float2 f = __half22float2(hp[k]);
                                acc[2*k]   = fmaf(wB, f.x, acc[2*k]);
                                acc[2*k+1] = fmaf(wB, f.y, acc[2*k+1]);
                            }
                        }
                    }
                }
            }
        }
        // channel avg / max across 8 local values then 8 lanes (full-warp shfl)
        float sum = 0.f, mx = -3.0e38f;
#pragma unroll
        for (int k = 0; k < 8; k++) { sum += acc[k]; mx = fmaxf(mx, acc[k]); }
#pragma unroll
        for (int off = 4; off; off >>= 1) {
            sum += __shfl_xor_sync(0xFFFFFFFFu, sum, off);
            mx = fmaxf(mx, __shfl_xor_sync(0xFFFFFFFFu, mx, off));
        }
        if (active) {
            // pack to fp16 and store (one 128B wavefront per point)
            __half2 hv[4];
#pragma unroll
            for (int k = 0; k < 4; k++)
                hv[k] = __floats2half2_rn(acc[2*k], acc[2*k+1]);
            *(uint4*)&v_sm2[p * 32 + lane * 4] = *(uint4*)hv;
            if (lane == 0) { savg[p] = sum * (1.0f / 64.0f); smax_[p] = mx; }
        }
    }
    __syncthreads();

    // ---- Stage 2: spatial attention gates for the 3*TL x 3 interior ----
    if (t < TL * 3 * 3) {
        int ra = t / 3, kw = t - ra * 3;   // interior row ra -> v-row ra+1
        float acc = __ldg(sa_b);
#pragma unroll
        for (int kh = 0; kh < 3; kh++) {
            int rr = ra + kh;              // v-row of s input (0..NR-1)
#pragma unroll
            for (int k2 = 0; k2 < 3; k2++) {
                int cc = kw + k2 - 1;      // column with zero padding
                if (cc >= 0 && cc < 3) {
                    int p = rr * 3 + cc;
                    acc += __ldg(&sa_w[kh * 3 + k2])     * savg[p]
                         + __ldg(&sa_w[9 + kh * 3 + k2]) * smax_[p];
                }
            }
        }
        m_att[t] = 1.0f + 1.0f / (1.0f + expf(-acc));   // y = (1+a)*v
    }
    __syncthreads();

    // ---- Stage 3: depthwise 3x3 (stride handled by patch layout) ----
    {
        int c2 = t & 31;           // half2 channel pair index (2 channels)
        int lg = t >> 5;           // 0..7
        int cA = 2 * c2, cB = 2 * c2 + 1;
        float dwA[9], dwB[9];
#pragma unroll
        for (int k = 0; k < 9; k++) { dwA[k] = dw_sm[cA * 9 + k]; dwB[k] = dw_sm[cB * 9 + k]; }
        float dbA = __ldg(&dw_b[cA]), dbB = __ldg(&dw_b[cB]);
#pragma unroll
        for (int li = 0; li < 2; li++) {
            int l = lg + li * 8;
            float a0 = dbA, a1 = dbB;
#pragma unroll
            for (int kh = 0; kh < 3; kh++)
#pragma unroll
                for (int kw = 0; kw < 3; kw++) {
                    int ra = 3 * l + kh;
                    float g = m_att[ra * 3 + kw];
                    float2 v = __half22float2(v_sm2[((ra + 1) * 3 + kw) * 32 + c2]);
                    a0 = fmaf(dwA[kh * 3 + kw] * g, v.x, a0);
                    a1 = fmaf(dwB[kh * 3 + kw] * g, v.y, a1);
                }
            z_sm[l * 64 + cA] = a0;
            z_sm[l * 64 + cB] = a1;
        }
    }
    __syncthreads();

    // ---- Stage 4: pointwise 64x64 (each thread: 1 o, 4 l) ----
    {
        int o = t & 63, lgrp = t >> 6;          // lgrp 0..3, l = 4*lgrp+j
        float pb = __ldg(&pw_b[o]);
        float a0 = pb, a1 = pb, a2 = pb, a3 = pb;
        const int lA = 4 * lgrp;
#pragma unroll
        for (int cc = 0; cc < 64; cc += 4) {
            float4 wv = *(const float4*)&pw_sm[o * 68 + cc];
            float4 z0 = *(const float4*)&z_sm[(lA + 0) * 64 + cc];
            float4 z1 = *(const float4*)&z_sm[(lA + 1) * 64 + cc];
            float4 z2 = *(const float4*)&z_sm[(lA + 2) * 64 + cc];
            float4 z3 = *(const float4*)&z_sm[(lA + 3) * 64 + cc];
            a0 = fmaf(wv.x, z0.x, a0); a0 = fmaf(wv.y, z0.y, a0);
            a0 = fmaf(wv.z, z0.z, a0); a0 = fmaf(wv.w, z0.w, a0);
            a1 = fmaf(wv.x, z1.x, a1); a1 = fmaf(wv.y, z1.y, a1);
            a1 = fmaf(wv.z, z1.z, a1); a1 = fmaf(wv.w, z1.w, a1);
            a2 = fmaf(wv.x, z2.x, a2); a2 = fmaf(wv.y, z2.y, a2);
            a2 = fmaf(wv.z, z2.z, a2); a2 = fmaf(wv.w, z2.w, a2);
            a3 = fmaf(wv.x, z3.x, a3); a3 = fmaf(wv.y, z3.y, a3);
            a3 = fmaf(wv.z, z3.z, a3); a3 = fmaf(wv.w, z3.w, a3);
        }
        o_sm[o * (TL + 1) + lA + 0] = a0;
        o_sm[o * (TL + 1) + lA + 1] = a1;
        o_sm[o * (TL + 1) + lA + 2] = a2;
        o_sm[o * (TL + 1) + lA + 3] = a3;
    }
    __syncthreads();

    // ---- Stage 5: coalesced write-out out[b, o, l0..l0+15] ----
    for (int i = t; i < 64 * TL; i += 256) {
        int o = i >> 4, j = i & 15;
        out[((size_t)b * 64 + o) * LOUT + l0 + j] = o_sm[o * (TL + 1) + j];
    }
}

// ---------------------------------------------------------------------------
extern "C" void kernel_launch(void* const* d_in, const int* in_sizes, int n_in,
                              void* d_out, int out_size) {
    (void)in_sizes; (void)n_in; (void)out_size;
    const float* x    = (const float*)d_in[0];
    const float* grid = (const float*)d_in[1];
    const float* sa_w = (const float*)d_in[2];
    const float* sa_b = (const float*)d_in[3];
    const float* dw_w = (const float*)d_in[4];
    const float* dw_b = (const float*)d_in[5];
    const float* pw_w = (const float*)d_in[6];
    const float* pw_b = (const float*)d_in[7];
    float* out = (float*)d_out;

    dim3 tb(32, 8);
    dim3 tg(Ww / 32, Cc / 32, Bsz * Hh);
    transpose_k<<<tg, tb>>>(x);

    dim3 mg(LOUT / TL, Bsz);
    fused_k<<<mg, 256>>>(grid, sa_w, sa_b, dw_w, dw_b, pw_w, pw_b, out);
}